// round 2
// baseline (speedup 1.0000x reference)
#include <cuda_runtime.h>
#include <math.h>

#define Bq 2
#define Cc 1024
#define Tt 2048
#define Hh 16
#define CHd 64
#define Gg 32

// ---------------- scratch (device globals; no allocations) ----------------
__device__ float g_xn[(size_t)Bq * Cc * Tt];          // GroupNorm output
__device__ float g_qkv[(size_t)Bq * 3 * Cc * Tt];     // QKV projection output
__device__ float g_a[(size_t)Bq * Cc * Tt];           // attention output (pre-proj)
__device__ float g_tab[Hh * (2 * Tt - 1)];            // per-head rel-pos bias by distance

// ---------------- relative-position bias table ----------------
// d = q_pos - k_pos in [-(T-1), T-1]; tab[h][d + T-1] = rel_emb[bucket(d)][h] * sqrt(CH)
__global__ void fill_tab_kernel(const float* __restrict__ rel_emb) {
    int idx = blockIdx.x * 256 + threadIdx.x;
    const int NT = Hh * (2 * Tt - 1);
    if (idx >= NT) return;
    int h = idx / (2 * Tt - 1);
    int di = idx % (2 * Tt - 1);
    int n = di - (Tt - 1);            // n = q - k  (matches reference: n = -(k-q))
    int ret = 0;
    if (n < 0) { ret = 16; n = -n; }
    int bucket;
    if (n < 8) {
        bucket = ret + n;
    } else {
        // 8 + int( log(n/8)/log(8) * 8 ), clamped to 15 (float32 math like jnp)
        float v = logf((float)n * 0.125f) / logf(8.0f) * 8.0f;
        int vi = 8 + (int)v;
        if (vi > 15) vi = 15;
        bucket = ret + vi;
    }
    g_tab[h * (2 * Tt - 1) + di] = rel_emb[bucket * Hh + h] * 8.0f; // RP_SCALE = sqrt(64)
}

// ---------------- GroupNorm ----------------
// one block per (b, g); group = 32 contiguous channels x T
__global__ __launch_bounds__(256) void gn_kernel(const float* __restrict__ x,
                                                 const float* __restrict__ w,
                                                 const float* __restrict__ bb) {
    int blk = blockIdx.x;
    int b = blk >> 5, g = blk & 31;
    const int CPG = Cc / Gg;              // 32
    const int NE = CPG * Tt;              // 65536
    const float* xp = x + ((size_t)b * Cc + (size_t)g * CPG) * Tt;
    float* op = g_xn + ((size_t)b * Cc + (size_t)g * CPG) * Tt;
    int tid = threadIdx.x;

    float s = 0.f, s2 = 0.f;
    for (int i = tid; i < NE; i += 256) {
        float v = xp[i];
        s += v;
        s2 = fmaf(v, v, s2);
    }
    for (int o = 16; o; o >>= 1) {
        s  += __shfl_xor_sync(0xffffffffu, s, o);
        s2 += __shfl_xor_sync(0xffffffffu, s2, o);
    }
    __shared__ float sh[2][8];
    int wid = tid >> 5, ln = tid & 31;
    if (ln == 0) { sh[0][wid] = s; sh[1][wid] = s2; }
    __syncthreads();
    if (tid == 0) {
        float a = 0.f, c = 0.f;
        for (int i = 0; i < 8; i++) { a += sh[0][i]; c += sh[1][i]; }
        float mu = a / (float)NE;
        float var = c / (float)NE - mu * mu;
        sh[0][0] = mu;
        sh[1][0] = rsqrtf(var + 1e-5f);
    }
    __syncthreads();
    float mu = sh[0][0], inv = sh[1][0];
    for (int i = tid; i < NE; i += 256) {
        int c = g * CPG + i / Tt;
        op[i] = (xp[i] - mu) * inv * w[c] + bb[c];
    }
}

// ---------------- SGEMM: out[m][n] = sum_k W[m][k] * X[k][n] + bias[m] (+resid) ----------------
// BM=BN=128, BK=8, 256 threads, 8x8 micro-tiles.
// PROJ=false: X = g_xn, Out = g_qkv, M = 3C.   PROJ=true: X = g_a, Out = outp, +resid, M = C.
template <bool PROJ>
__global__ __launch_bounds__(256) void sgemm_kernel(const float* __restrict__ W,
                                                    const float* __restrict__ bias,
                                                    const float* __restrict__ resid,
                                                    float* __restrict__ outp) {
    const int N = Tt;
    const int K = Cc;
    int b = blockIdx.z;
    const float* Xb = (PROJ ? g_a : g_xn) + (size_t)b * Cc * Tt;
    float* Ob = PROJ ? (outp + (size_t)b * Cc * Tt)
                     : (g_qkv + (size_t)b * 3 * Cc * Tt);
    const float* Rb = PROJ ? (resid + (size_t)b * Cc * Tt) : nullptr;

    int m0 = blockIdx.y * 128, n0 = blockIdx.x * 128;
    __shared__ __align__(16) float As[8][128];
    __shared__ __align__(16) float Bs[8][128];

    int tid = threadIdx.x;
    int tx = tid & 15, ty = tid >> 4;
    int arow = tid >> 1, akq = (tid & 1) * 4;
    int brow = tid >> 5, bcol = (tid & 31) * 4;

    float acc[8][8];
#pragma unroll
    for (int i = 0; i < 8; i++)
#pragma unroll
        for (int j = 0; j < 8; j++) acc[i][j] = 0.f;

    for (int kt = 0; kt < K; kt += 8) {
        float4 wa = *(const float4*)&W[(size_t)(m0 + arow) * K + kt + akq];
        float4 xb = *(const float4*)&Xb[(size_t)(kt + brow) * N + n0 + bcol];
        __syncthreads();
        As[akq + 0][arow] = wa.x;
        As[akq + 1][arow] = wa.y;
        As[akq + 2][arow] = wa.z;
        As[akq + 3][arow] = wa.w;
        *(float4*)&Bs[brow][bcol] = xb;
        __syncthreads();
#pragma unroll
        for (int kk = 0; kk < 8; kk++) {
            float4 a0 = *(const float4*)&As[kk][ty * 8];
            float4 a1 = *(const float4*)&As[kk][ty * 8 + 4];
            float4 b0 = *(const float4*)&Bs[kk][tx * 8];
            float4 b1 = *(const float4*)&Bs[kk][tx * 8 + 4];
            float av[8] = {a0.x, a0.y, a0.z, a0.w, a1.x, a1.y, a1.z, a1.w};
            float bv[8] = {b0.x, b0.y, b0.z, b0.w, b1.x, b1.y, b1.z, b1.w};
#pragma unroll
            for (int i = 0; i < 8; i++)
#pragma unroll
                for (int j = 0; j < 8; j++)
                    acc[i][j] = fmaf(av[i], bv[j], acc[i][j]);
        }
    }

#pragma unroll
    for (int i = 0; i < 8; i++) {
        int m = m0 + ty * 8 + i;
        float bv = bias[m];
        size_t ro = (size_t)m * N + n0 + tx * 8;
        float o[8];
#pragma unroll
        for (int j = 0; j < 8; j++) o[j] = acc[i][j] + bv;
        if (PROJ) {
            float4 r0 = *(const float4*)&Rb[ro];
            float4 r1 = *(const float4*)&Rb[ro + 4];
            o[0] += r0.x; o[1] += r0.y; o[2] += r0.z; o[3] += r0.w;
            o[4] += r1.x; o[5] += r1.y; o[6] += r1.z; o[7] += r1.w;
        }
        float4 w0 = make_float4(o[0], o[1], o[2], o[3]);
        float4 w1 = make_float4(o[4], o[5], o[6], o[7]);
        *(float4*)&Ob[ro] = w0;
        *(float4*)&Ob[ro + 4] = w1;
    }
}

// ---------------- fused flash attention ----------------
// grid: (T/64, H, B), 256 threads. 64-row Q tile, stream over K/V tiles of 64.
// Qs[d][r], KP[d][c] (K) then reused as P[r][c], Vs[c][d^swz]. 48KB static smem total.
__global__ __launch_bounds__(256) void attn_kernel() {
    __shared__ __align__(16) float Qs[64][64];
    __shared__ __align__(16) float KP[64][64];
    __shared__ __align__(16) float Vs[64][64];

    int q0 = blockIdx.x * 64;
    int h = blockIdx.y;
    int b = blockIdx.z;
    int tid = threadIdx.x, tx = tid & 15, ty = tid >> 4;
    const float scale = 0.35355339059327373f;   // 1 / 64^(1/4)

    const float* qp = g_qkv + ((size_t)b * 3 * Cc + (size_t)h * 3 * CHd) * Tt;
    const float* kp = qp + (size_t)CHd * Tt;
    const float* vp = qp + (size_t)2 * CHd * Tt;

    for (int idx = tid; idx < 64 * 64; idx += 256) {
        int d = idx >> 6, r = idx & 63;
        Qs[d][r] = qp[(size_t)d * Tt + q0 + r] * scale;
    }

    float acc[4][4];
    float mrow[4], lrow[4];
#pragma unroll
    for (int i = 0; i < 4; i++) {
        mrow[i] = -3.0e38f;
        lrow[i] = 0.f;
#pragma unroll
        for (int j = 0; j < 4; j++) acc[i][j] = 0.f;
    }
    const float* tb = g_tab + h * (2 * Tt - 1) + (Tt - 1);

    for (int k0 = 0; k0 < Tt; k0 += 64) {
        __syncthreads();  // prev O-GEMM done reading KP(P)/Vs
        for (int idx = tid; idx < 64 * 64; idx += 256) {
            int d = idx >> 6, c = idx & 63;
            KP[d][c] = kp[(size_t)d * Tt + k0 + c] * scale;
            Vs[c][d ^ ((c & 7) << 2)] = vp[(size_t)d * Tt + k0 + c];
        }
        __syncthreads();

        // S[r][c] = sum_d Q[r][d] * K[c][d]
        float s[4][4];
#pragma unroll
        for (int i = 0; i < 4; i++)
#pragma unroll
            for (int j = 0; j < 4; j++) s[i][j] = 0.f;
#pragma unroll 16
        for (int d = 0; d < 64; d++) {
            float4 fq = *(const float4*)&Qs[d][ty * 4];
            float4 fk = *(const float4*)&KP[d][tx * 4];
            float qv[4] = {fq.x, fq.y, fq.z, fq.w};
            float kv[4] = {fk.x, fk.y, fk.z, fk.w};
#pragma unroll
            for (int i = 0; i < 4; i++)
#pragma unroll
                for (int j = 0; j < 4; j++)
                    s[i][j] = fmaf(qv[i], kv[j], s[i][j]);
        }

        // bias + online softmax (rows owned by 16-lane groups; butterfly width 16)
        int base = q0 - k0 + ty * 4 - tx * 4;
        float p[4][4];
#pragma unroll
        for (int i = 0; i < 4; i++) {
#pragma unroll
            for (int j = 0; j < 4; j++) p[i][j] = s[i][j] + tb[base + i - j];
            float tmax = fmaxf(fmaxf(p[i][0], p[i][1]), fmaxf(p[i][2], p[i][3]));
#pragma unroll
            for (int o = 8; o; o >>= 1)
                tmax = fmaxf(tmax, __shfl_xor_sync(0xffffffffu, tmax, o, 16));
            float mn = fmaxf(mrow[i], tmax);
            float sc = __expf(mrow[i] - mn);
            float rs = 0.f;
#pragma unroll
            for (int j = 0; j < 4; j++) {
                p[i][j] = __expf(p[i][j] - mn);
                rs += p[i][j];
            }
#pragma unroll
            for (int o = 8; o; o >>= 1)
                rs += __shfl_xor_sync(0xffffffffu, rs, o, 16);
            lrow[i] = lrow[i] * sc + rs;
            mrow[i] = mn;
#pragma unroll
            for (int j = 0; j < 4; j++) acc[i][j] *= sc;
        }

        __syncthreads();  // everyone done reading KP as K
#pragma unroll
        for (int i = 0; i < 4; i++)
#pragma unroll
            for (int j = 0; j < 4; j++)
                KP[ty * 4 + i][tx * 4 + j] = p[i][j];
        __syncthreads();  // P visible

        // O[r][d] += sum_c P[r][c] * V[c][d]
#pragma unroll 16
        for (int c = 0; c < 64; c++) {
            float4 fv = *(const float4*)&Vs[c][(tx * 4) ^ ((c & 7) << 2)];
            float vv[4] = {fv.x, fv.y, fv.z, fv.w};
#pragma unroll
            for (int i = 0; i < 4; i++) {
                float pp = KP[ty * 4 + i][c];
#pragma unroll
                for (int j = 0; j < 4; j++)
                    acc[i][j] = fmaf(pp, vv[j], acc[i][j]);
            }
        }
    }

#pragma unroll
    for (int i = 0; i < 4; i++) {
        float inv = 1.0f / lrow[i];
#pragma unroll
        for (int j = 0; j < 4; j++)
            g_a[((size_t)b * Cc + (size_t)h * CHd + tx * 4 + j) * Tt + q0 + ty * 4 + i] =
                acc[i][j] * inv;
    }
}

// ---------------- launch ----------------
extern "C" void kernel_launch(void* const* d_in, const int* in_sizes, int n_in,
                              void* d_out, int out_size) {
    const float* x       = (const float*)d_in[0];
    const float* gn_w    = (const float*)d_in[1];
    const float* gn_b    = (const float*)d_in[2];
    const float* qkv_w   = (const float*)d_in[3];
    const float* qkv_b   = (const float*)d_in[4];
    const float* proj_w  = (const float*)d_in[5];
    const float* proj_b  = (const float*)d_in[6];
    const float* rel_emb = (const float*)d_in[7];
    float* out = (float*)d_out;
    (void)in_sizes; (void)n_in; (void)out_size;

    fill_tab_kernel<<<(Hh * (2 * Tt - 1) + 255) / 256, 256>>>(rel_emb);
    gn_kernel<<<Bq * Gg, 256>>>(x, gn_w, gn_b);
    sgemm_kernel<false><<<dim3(Tt / 128, (3 * Cc) / 128, Bq), 256>>>(qkv_w, qkv_b, nullptr, nullptr);
    attn_kernel<<<dim3(Tt / 64, Hh, Bq), 256>>>();
    sgemm_kernel<true><<<dim3(Tt / 128, Cc / 128, Bq), 256>>>(proj_w, proj_b, x, out);
}

// round 3
// speedup vs baseline: 1.2097x; 1.2097x over previous
#include <cuda_runtime.h>
#include <math.h>
#include <stdint.h>

#define Bq 2
#define Cc 1024
#define Tt 2048
#define Hh 16
#define CHd 64
#define Gg 32

// ---------------- scratch (device globals; no allocations) ----------------
__device__ float g_xn[(size_t)Bq * Cc * Tt];          // GroupNorm output
__device__ float g_qkv[(size_t)Bq * 3 * Cc * Tt];     // QKV projection output
__device__ float g_a[(size_t)Bq * Cc * Tt];           // attention output (pre-proj)
__device__ float g_tab[Hh * (2 * Tt - 1)];            // per-head rel-pos bias by distance

// ---------------- relative-position bias table ----------------
__global__ void fill_tab_kernel(const float* __restrict__ rel_emb) {
    int idx = blockIdx.x * 256 + threadIdx.x;
    const int NT = Hh * (2 * Tt - 1);
    if (idx >= NT) return;
    int h = idx / (2 * Tt - 1);
    int di = idx % (2 * Tt - 1);
    int n = di - (Tt - 1);            // n = q - k
    int ret = 0;
    if (n < 0) { ret = 16; n = -n; }
    int bucket;
    if (n < 8) {
        bucket = ret + n;
    } else {
        float v = logf((float)n * 0.125f) / logf(8.0f) * 8.0f;
        int vi = 8 + (int)v;
        if (vi > 15) vi = 15;
        bucket = ret + vi;
    }
    g_tab[h * (2 * Tt - 1) + di] = rel_emb[bucket * Hh + h] * 8.0f; // RP_SCALE = 8
}

// ---------------- GroupNorm ----------------
__global__ __launch_bounds__(256) void gn_kernel(const float* __restrict__ x,
                                                 const float* __restrict__ w,
                                                 const float* __restrict__ bb) {
    int blk = blockIdx.x;
    int b = blk >> 5, g = blk & 31;
    const int CPG = Cc / Gg;
    const int NE = CPG * Tt;
    const float* xp = x + ((size_t)b * Cc + (size_t)g * CPG) * Tt;
    float* op = g_xn + ((size_t)b * Cc + (size_t)g * CPG) * Tt;
    int tid = threadIdx.x;

    float s = 0.f, s2 = 0.f;
    for (int i = tid; i < NE; i += 256) {
        float v = xp[i];
        s += v;
        s2 = fmaf(v, v, s2);
    }
    for (int o = 16; o; o >>= 1) {
        s  += __shfl_xor_sync(0xffffffffu, s, o);
        s2 += __shfl_xor_sync(0xffffffffu, s2, o);
    }
    __shared__ float sh[2][8];
    int wid = tid >> 5, ln = tid & 31;
    if (ln == 0) { sh[0][wid] = s; sh[1][wid] = s2; }
    __syncthreads();
    if (tid == 0) {
        float a = 0.f, c = 0.f;
        for (int i = 0; i < 8; i++) { a += sh[0][i]; c += sh[1][i]; }
        float mu = a / (float)NE;
        float var = c / (float)NE - mu * mu;
        sh[0][0] = mu;
        sh[1][0] = rsqrtf(var + 1e-5f);
    }
    __syncthreads();
    float mu = sh[0][0], inv = sh[1][0];
    for (int i = tid; i < NE; i += 256) {
        int c = g * CPG + i / Tt;
        op[i] = (xp[i] - mu) * inv * w[c] + bb[c];
    }
}

// ---------------- tf32 tensor-core GEMM ----------------
// out[m][n] = sum_k W[m][k] * X[k][n] + bias[m] (+resid)
// Block 128x128, BK=16, 256 threads = 8 warps in 2(M)x4(N); warp tile 64x32.
// Fragment-packed smem: each lane's mma fragment is contiguous (uint4 / uint2).
__device__ __forceinline__ unsigned f2tf(float f) {
    unsigned u;
    asm("cvt.rna.tf32.f32 %0, %1;" : "=r"(u) : "f"(f));
    return u;
}

template <bool PROJ>
__global__ __launch_bounds__(256, 2) void mma_gemm(const float* __restrict__ Wt,
                                                   const float* __restrict__ bias,
                                                   const float* __restrict__ resid,
                                                   float* __restrict__ outp) {
    const int N = Tt, K = Cc;
    int b = blockIdx.z;
    const float* Xb = (PROJ ? g_a : g_xn) + (size_t)b * Cc * Tt;
    float* Ob = PROJ ? (outp + (size_t)b * Cc * Tt) : (g_qkv + (size_t)b * 3 * Cc * Tt);
    const float* Rb = PROJ ? (resid + (size_t)b * Cc * Tt) : nullptr;

    int m0 = blockIdx.y * 128, n0 = blockIdx.x * 128;

    // [k-step][tile][lane][slot]
    __shared__ unsigned Apack[2][8][32][4];    // 8 KB
    __shared__ unsigned Bpack[2][16][32][2];   // 8 KB

    int tid = threadIdx.x, lane = tid & 31, warp = tid >> 5;
    int wm = warp & 1, wn = warp >> 1;

    // A staging coords: thread t -> row mm = t/2, k-chunk (t&1)*8
    int amm = tid >> 1;
    int akk = (tid & 1) * 8;
    int as_ = tid & 1;
    int atm = amm >> 4, ar = amm & 15;
    int asl = ar >> 3;                         // slot low bit (r>=8)
    unsigned* abase = &Apack[as_][atm][(ar & 7) * 4][0];

    // B staging coords: thread t -> k row = t/16, n-chunk (t&15)*8
    int bkk = tid >> 4;
    int bnn = (tid & 15) * 8;
    int bs_ = bkk >> 3, bc = bkk & 7, btn = tid & 15;
    int bo = (bc & 3) * 2 + (bc >> 2);
    unsigned* bbase = &Bpack[bs_][btn][0][0];

    float acc[4][4][4];
#pragma unroll
    for (int i = 0; i < 4; i++)
#pragma unroll
        for (int j = 0; j < 4; j++)
#pragma unroll
            for (int q = 0; q < 4; q++) acc[i][j][q] = 0.f;

    for (int kt = 0; kt < K; kt += 16) {
        float4 wa0 = *(const float4*)&Wt[(size_t)(m0 + amm) * K + kt + akk];
        float4 wa1 = *(const float4*)&Wt[(size_t)(m0 + amm) * K + kt + akk + 4];
        float4 xb0 = *(const float4*)&Xb[(size_t)(kt + bkk) * N + n0 + bnn];
        float4 xb1 = *(const float4*)&Xb[(size_t)(kt + bkk) * N + n0 + bnn + 4];
        __syncthreads();
        // A scatter: value (r, c) -> lane (r&7)*4 + (c&3), slot (c>=4)*2 + (r>=8)
        abase[0 * 4 + asl]     = f2tf(wa0.x);
        abase[1 * 4 + asl]     = f2tf(wa0.y);
        abase[2 * 4 + asl]     = f2tf(wa0.z);
        abase[3 * 4 + asl]     = f2tf(wa0.w);
        abase[0 * 4 + asl + 2] = f2tf(wa1.x);
        abase[1 * 4 + asl + 2] = f2tf(wa1.y);
        abase[2 * 4 + asl + 2] = f2tf(wa1.z);
        abase[3 * 4 + asl + 2] = f2tf(wa1.w);
        // B scatter: value (kc, n) -> lane (n&7)*4 + (kc&3), slot (kc>=4)
        bbase[0 * 8 + bo]  = f2tf(xb0.x);
        bbase[1 * 8 + bo]  = f2tf(xb0.y);
        bbase[2 * 8 + bo]  = f2tf(xb0.z);
        bbase[3 * 8 + bo]  = f2tf(xb0.w);
        bbase[4 * 8 + bo]  = f2tf(xb1.x);
        bbase[5 * 8 + bo]  = f2tf(xb1.y);
        bbase[6 * 8 + bo]  = f2tf(xb1.z);
        bbase[7 * 8 + bo]  = f2tf(xb1.w);
        __syncthreads();

#pragma unroll
        for (int s = 0; s < 2; s++) {
            uint4 af[4];
            uint2 bf[4];
#pragma unroll
            for (int tm = 0; tm < 4; tm++)
                af[tm] = *(const uint4*)&Apack[s][wm * 4 + tm][lane][0];
#pragma unroll
            for (int tn = 0; tn < 4; tn++)
                bf[tn] = *(const uint2*)&Bpack[s][wn * 4 + tn][lane][0];
#pragma unroll
            for (int tm = 0; tm < 4; tm++)
#pragma unroll
                for (int tn = 0; tn < 4; tn++)
                    asm volatile(
                        "mma.sync.aligned.m16n8k8.row.col.f32.tf32.tf32.f32 "
                        "{%0,%1,%2,%3}, {%4,%5,%6,%7}, {%8,%9}, {%0,%1,%2,%3};"
                        : "+f"(acc[tm][tn][0]), "+f"(acc[tm][tn][1]),
                          "+f"(acc[tm][tn][2]), "+f"(acc[tm][tn][3])
                        : "r"(af[tm].x), "r"(af[tm].y), "r"(af[tm].z), "r"(af[tm].w),
                          "r"(bf[tn].x), "r"(bf[tn].y));
        }
    }

    // epilogue: c0 (r, 2c) c1 (r, 2c+1) c2 (r+8, 2c) c3 (r+8, 2c+1)
    int gid = lane >> 2, tg = lane & 3;
#pragma unroll
    for (int tm = 0; tm < 4; tm++) {
        int rr = m0 + wm * 64 + tm * 16 + gid;
        float b0v = bias[rr], b1v = bias[rr + 8];
#pragma unroll
        for (int tn = 0; tn < 4; tn++) {
            int cc = n0 + wn * 32 + tn * 8 + tg * 2;
            size_t o0 = (size_t)rr * N + cc;
            size_t o1 = (size_t)(rr + 8) * N + cc;
            float2 v0 = make_float2(acc[tm][tn][0] + b0v, acc[tm][tn][1] + b0v);
            float2 v1 = make_float2(acc[tm][tn][2] + b1v, acc[tm][tn][3] + b1v);
            if (PROJ) {
                float2 r0 = *(const float2*)&Rb[o0];
                float2 r1 = *(const float2*)&Rb[o1];
                v0.x += r0.x; v0.y += r0.y;
                v1.x += r1.x; v1.y += r1.y;
            }
            *(float2*)&Ob[o0] = v0;
            *(float2*)&Ob[o1] = v1;
        }
    }
}

// ---------------- fused flash attention (8x4 microtile, 128 threads) ----------------
// grid: (T/64, H, B). 64-row Q tile, stream over 64-col K/V tiles.
// Qs[d][r]; KP[d][c] holds K then is overlaid with P[r][c]; Vs[c][d^swz].
__global__ __launch_bounds__(128) void attn_kernel() {
    __shared__ __align__(16) float Qs[64][64];
    __shared__ __align__(16) float KP[64][64];
    __shared__ __align__(16) float Vs[64][64];

    int q0 = blockIdx.x * 64;
    int h = blockIdx.y;
    int b = blockIdx.z;
    int tid = threadIdx.x, tx = tid & 15, ty = tid >> 4;   // ty 0..7 -> 8 rows each
    const float scale = 0.35355339059327373f;              // 64^(-1/4)

    const float* qp = g_qkv + ((size_t)b * 3 * Cc + (size_t)h * 3 * CHd) * Tt;
    const float* kp = qp + (size_t)CHd * Tt;
    const float* vp = qp + (size_t)2 * CHd * Tt;

    for (int idx = tid * 4; idx < 64 * 64; idx += 128 * 4) {
        int d = idx >> 6, r = idx & 63;
        float4 v = *(const float4*)&qp[(size_t)d * Tt + q0 + r];
        v.x *= scale; v.y *= scale; v.z *= scale; v.w *= scale;
        *(float4*)&Qs[d][r] = v;
    }

    float acc[8][4], mrow[8], lrow[8];
#pragma unroll
    for (int i = 0; i < 8; i++) {
        mrow[i] = -3.0e38f;
        lrow[i] = 0.f;
#pragma unroll
        for (int j = 0; j < 4; j++) acc[i][j] = 0.f;
    }
    const float* tb = g_tab + h * (2 * Tt - 1) + (Tt - 1);

    for (int k0 = 0; k0 < Tt; k0 += 64) {
        __syncthreads();  // prev PV done reading KP(P)/Vs
        for (int idx = tid * 4; idx < 64 * 64; idx += 128 * 4) {
            int d = idx >> 6, c = idx & 63;
            float4 v = *(const float4*)&kp[(size_t)d * Tt + k0 + c];
            v.x *= scale; v.y *= scale; v.z *= scale; v.w *= scale;
            *(float4*)&KP[d][c] = v;
        }
        for (int idx = tid; idx < 64 * 64; idx += 128) {
            int d = idx >> 6, c = idx & 63;
            Vs[c][d ^ ((c & 7) << 2)] = vp[(size_t)d * Tt + k0 + c];
        }
        __syncthreads();

        // S[r][c] = sum_d Q[r][d] * K[c][d]
        float p[8][4];
#pragma unroll
        for (int i = 0; i < 8; i++)
#pragma unroll
            for (int j = 0; j < 4; j++) p[i][j] = 0.f;
#pragma unroll 8
        for (int d = 0; d < 64; d++) {
            float4 qa = *(const float4*)&Qs[d][ty * 8];
            float4 qb = *(const float4*)&Qs[d][ty * 8 + 4];
            float4 fk = *(const float4*)&KP[d][tx * 4];
            float qv[8] = {qa.x, qa.y, qa.z, qa.w, qb.x, qb.y, qb.z, qb.w};
            float kv[4] = {fk.x, fk.y, fk.z, fk.w};
#pragma unroll
            for (int i = 0; i < 8; i++)
#pragma unroll
                for (int j = 0; j < 4; j++)
                    p[i][j] = fmaf(qv[i], kv[j], p[i][j]);
        }

        // bias + online softmax (rows in 16-lane groups; butterfly width 16)
        int base = q0 - k0 + ty * 8 - tx * 4;
#pragma unroll
        for (int i = 0; i < 8; i++) {
#pragma unroll
            for (int j = 0; j < 4; j++) p[i][j] += tb[base + i - j];
            float tmax = fmaxf(fmaxf(p[i][0], p[i][1]), fmaxf(p[i][2], p[i][3]));
#pragma unroll
            for (int o = 8; o; o >>= 1)
                tmax = fmaxf(tmax, __shfl_xor_sync(0xffffffffu, tmax, o, 16));
            float mn = fmaxf(mrow[i], tmax);
            float sc = __expf(mrow[i] - mn);
            float rs = 0.f;
#pragma unroll
            for (int j = 0; j < 4; j++) {
                p[i][j] = __expf(p[i][j] - mn);
                rs += p[i][j];
            }
#pragma unroll
            for (int o = 8; o; o >>= 1)
                rs += __shfl_xor_sync(0xffffffffu, rs, o, 16);
            lrow[i] = lrow[i] * sc + rs;
            mrow[i] = mn;
#pragma unroll
            for (int j = 0; j < 4; j++) acc[i][j] *= sc;
        }

        __syncthreads();  // done reading KP as K
#pragma unroll
        for (int i = 0; i < 8; i++)
            *(float4*)&KP[ty * 8 + i][tx * 4] = make_float4(p[i][0], p[i][1], p[i][2], p[i][3]);
        __syncthreads();  // P visible

        // O[r][d] += sum_c P[r][c] * V[c][d]
#pragma unroll 8
        for (int c = 0; c < 64; c++) {
            float4 fv = *(const float4*)&Vs[c][(tx * 4) ^ ((c & 7) << 2)];
            float vv[4] = {fv.x, fv.y, fv.z, fv.w};
#pragma unroll
            for (int i = 0; i < 8; i++) {
                float pp = KP[ty * 8 + i][c];
#pragma unroll
                for (int j = 0; j < 4; j++)
                    acc[i][j] = fmaf(pp, vv[j], acc[i][j]);
            }
        }
    }

#pragma unroll
    for (int i = 0; i < 8; i++) {
        float inv = 1.0f / lrow[i];
#pragma unroll
        for (int j = 0; j < 4; j++)
            g_a[((size_t)b * Cc + (size_t)h * CHd + tx * 4 + j) * Tt + q0 + ty * 8 + i] =
                acc[i][j] * inv;
    }
}

// ---------------- launch ----------------
extern "C" void kernel_launch(void* const* d_in, const int* in_sizes, int n_in,
                              void* d_out, int out_size) {
    const float* x       = (const float*)d_in[0];
    const float* gn_w    = (const float*)d_in[1];
    const float* gn_b    = (const float*)d_in[2];
    const float* qkv_w   = (const float*)d_in[3];
    const float* qkv_b   = (const float*)d_in[4];
    const float* proj_w  = (const float*)d_in[5];
    const float* proj_b  = (const float*)d_in[6];
    const float* rel_emb = (const float*)d_in[7];
    float* out = (float*)d_out;
    (void)in_sizes; (void)n_in; (void)out_size;

    fill_tab_kernel<<<(Hh * (2 * Tt - 1) + 255) / 256, 256>>>(rel_emb);
    gn_kernel<<<Bq * Gg, 256>>>(x, gn_w, gn_b);
    mma_gemm<false><<<dim3(Tt / 128, (3 * Cc) / 128, Bq), 256>>>(qkv_w, qkv_b, nullptr, nullptr);
    attn_kernel<<<dim3(Tt / 64, Hh, Bq), 128>>>();
    mma_gemm<true><<<dim3(Tt / 128, Cc / 128, Bq), 256>>>(proj_w, proj_b, x, out);
}

// round 4
// speedup vs baseline: 1.7780x; 1.4698x over previous
#include <cuda_runtime.h>
#include <math.h>
#include <stdint.h>

#define Bq 2
#define Cc 1024
#define Tt 2048
#define Hh 16
#define CHd 64
#define Gg 32

// ---------------- scratch (device globals; no allocations) ----------------
__device__ float g_xn[(size_t)Bq * Cc * Tt];
__device__ float g_qkv[(size_t)Bq * 3 * Cc * Tt];
__device__ float g_a[(size_t)Bq * Cc * Tt];
__device__ float g_tab[Hh * (2 * Tt - 1)];

// ---------------- relative-position bias table ----------------
__global__ void fill_tab_kernel(const float* __restrict__ rel_emb) {
    int idx = blockIdx.x * 256 + threadIdx.x;
    const int NT = Hh * (2 * Tt - 1);
    if (idx >= NT) return;
    int h = idx / (2 * Tt - 1);
    int di = idx % (2 * Tt - 1);
    int n = di - (Tt - 1);            // n = q - k
    int ret = 0;
    if (n < 0) { ret = 16; n = -n; }
    int bucket;
    if (n < 8) {
        bucket = ret + n;
    } else {
        float v = logf((float)n * 0.125f) / logf(8.0f) * 8.0f;
        int vi = 8 + (int)v;
        if (vi > 15) vi = 15;
        bucket = ret + vi;
    }
    g_tab[h * (2 * Tt - 1) + di] = rel_emb[bucket * Hh + h] * 8.0f;
}

// ---------------- GroupNorm ----------------
__global__ __launch_bounds__(256) void gn_kernel(const float* __restrict__ x,
                                                 const float* __restrict__ w,
                                                 const float* __restrict__ bb) {
    int blk = blockIdx.x;
    int b = blk >> 5, g = blk & 31;
    const int CPG = Cc / Gg;
    const int NE = CPG * Tt;
    const float* xp = x + ((size_t)b * Cc + (size_t)g * CPG) * Tt;
    float* op = g_xn + ((size_t)b * Cc + (size_t)g * CPG) * Tt;
    int tid = threadIdx.x;

    float s = 0.f, s2 = 0.f;
    for (int i = tid; i < NE; i += 256) {
        float v = xp[i];
        s += v;
        s2 = fmaf(v, v, s2);
    }
    for (int o = 16; o; o >>= 1) {
        s  += __shfl_xor_sync(0xffffffffu, s, o);
        s2 += __shfl_xor_sync(0xffffffffu, s2, o);
    }
    __shared__ float sh[2][8];
    int wid = tid >> 5, ln = tid & 31;
    if (ln == 0) { sh[0][wid] = s; sh[1][wid] = s2; }
    __syncthreads();
    if (tid == 0) {
        float a = 0.f, c = 0.f;
        for (int i = 0; i < 8; i++) { a += sh[0][i]; c += sh[1][i]; }
        float mu = a / (float)NE;
        float var = c / (float)NE - mu * mu;
        sh[0][0] = mu;
        sh[1][0] = rsqrtf(var + 1e-5f);
    }
    __syncthreads();
    float mu = sh[0][0], inv = sh[1][0];
    for (int i = tid; i < NE; i += 256) {
        int c = g * CPG + i / Tt;
        op[i] = (xp[i] - mu) * inv * w[c] + bb[c];
    }
}

__device__ __forceinline__ unsigned f2tf(float f) {
    unsigned u;
    asm("cvt.rna.tf32.f32 %0, %1;" : "=r"(u) : "f"(f));
    return u;
}

#define MMA_TF32(C0,C1,C2,C3,A0,A1,A2,A3,B0,B1) \
    asm volatile("mma.sync.aligned.m16n8k8.row.col.f32.tf32.tf32.f32 " \
                 "{%0,%1,%2,%3}, {%4,%5,%6,%7}, {%8,%9}, {%0,%1,%2,%3};" \
                 : "+f"(C0), "+f"(C1), "+f"(C2), "+f"(C3) \
                 : "r"(A0), "r"(A1), "r"(A2), "r"(A3), "r"(B0), "r"(B1))

// ---------------- tf32 tensor-core GEMM, double-buffered ----------------
template <bool PROJ>
__global__ __launch_bounds__(256, 2) void mma_gemm(const float* __restrict__ Wt,
                                                   const float* __restrict__ bias,
                                                   const float* __restrict__ resid,
                                                   float* __restrict__ outp) {
    const int N = Tt, K = Cc;
    int b = blockIdx.z;
    const float* Xb = (PROJ ? g_a : g_xn) + (size_t)b * Cc * Tt;
    float* Ob = PROJ ? (outp + (size_t)b * Cc * Tt) : (g_qkv + (size_t)b * 3 * Cc * Tt);
    const float* Rb = PROJ ? (resid + (size_t)b * Cc * Tt) : nullptr;

    int m0 = blockIdx.y * 128, n0 = blockIdx.x * 128;

    __shared__ unsigned Apack[2][2][8][32][4];    // [stage][khalf][mtile][lane][slot] 16KB
    __shared__ unsigned Bpack[2][2][16][32][2];   // 16KB

    int tid = threadIdx.x, lane = tid & 31, warp = tid >> 5;
    int wm = warp & 1, wn = warp >> 1;

    int amm = tid >> 1;
    int akk = (tid & 1) * 8;
    int as_ = tid & 1;
    int atm = amm >> 4, ar = amm & 15;
    int asl = ar >> 3;
    const int ASTG = 2 * 8 * 32 * 4;
    unsigned* Afl = &Apack[0][0][0][0][0];
    int aob = ((as_ * 8 + atm) * 32 + (ar & 7) * 4) * 4;

    int bkk = tid >> 4;
    int bnn = (tid & 15) * 8;
    int bs_ = bkk >> 3, bc = bkk & 7, btn = tid & 15;
    int bo = (bc & 3) * 2 + (bc >> 2);
    const int BSTG = 2 * 16 * 32 * 2;
    unsigned* Bfl = &Bpack[0][0][0][0][0];
    int bob = ((bs_ * 16 + btn) * 32) * 2;

    float acc[4][4][4];
#pragma unroll
    for (int i = 0; i < 4; i++)
#pragma unroll
        for (int j = 0; j < 4; j++)
#pragma unroll
            for (int q = 0; q < 4; q++) acc[i][j][q] = 0.f;

    const float* wptr = &Wt[(size_t)(m0 + amm) * K + akk];
    const float* xptr = &Xb[(size_t)bkk * N + n0 + bnn];

    float4 wa0 = *(const float4*)(wptr);
    float4 wa1 = *(const float4*)(wptr + 4);
    float4 xb0 = *(const float4*)(xptr);
    float4 xb1 = *(const float4*)(xptr + 4);

#define STAGE_STORE(STG) do { \
    unsigned* ab = Afl + (STG) * ASTG + aob; \
    ab[0 * 4 + asl]     = f2tf(wa0.x); ab[1 * 4 + asl]     = f2tf(wa0.y); \
    ab[2 * 4 + asl]     = f2tf(wa0.z); ab[3 * 4 + asl]     = f2tf(wa0.w); \
    ab[0 * 4 + asl + 2] = f2tf(wa1.x); ab[1 * 4 + asl + 2] = f2tf(wa1.y); \
    ab[2 * 4 + asl + 2] = f2tf(wa1.z); ab[3 * 4 + asl + 2] = f2tf(wa1.w); \
    unsigned* bb2 = Bfl + (STG) * BSTG + bob; \
    bb2[0 * 8 + bo] = f2tf(xb0.x); bb2[1 * 8 + bo] = f2tf(xb0.y); \
    bb2[2 * 8 + bo] = f2tf(xb0.z); bb2[3 * 8 + bo] = f2tf(xb0.w); \
    bb2[4 * 8 + bo] = f2tf(xb1.x); bb2[5 * 8 + bo] = f2tf(xb1.y); \
    bb2[6 * 8 + bo] = f2tf(xb1.z); bb2[7 * 8 + bo] = f2tf(xb1.w); \
} while (0)

    STAGE_STORE(0);
    __syncthreads();

    for (int kt = 0; kt < K; kt += 16) {
        int st = (kt >> 4) & 1;
        bool more = (kt + 16) < K;
        if (more) {
            wa0 = *(const float4*)(wptr + kt + 16);
            wa1 = *(const float4*)(wptr + kt + 20);
            xb0 = *(const float4*)(xptr + (size_t)(kt + 16) * N);
            xb1 = *(const float4*)(xptr + (size_t)(kt + 16) * N + 4);
        }
#pragma unroll
        for (int s = 0; s < 2; s++) {
            uint4 af[4];
            uint2 bf[4];
#pragma unroll
            for (int tm = 0; tm < 4; tm++)
                af[tm] = *(const uint4*)(Afl + st * ASTG + ((s * 8 + wm * 4 + tm) * 32 + lane) * 4);
#pragma unroll
            for (int tn = 0; tn < 4; tn++)
                bf[tn] = *(const uint2*)(Bfl + st * BSTG + ((s * 16 + wn * 4 + tn) * 32 + lane) * 2);
#pragma unroll
            for (int tm = 0; tm < 4; tm++)
#pragma unroll
                for (int tn = 0; tn < 4; tn++)
                    MMA_TF32(acc[tm][tn][0], acc[tm][tn][1], acc[tm][tn][2], acc[tm][tn][3],
                             af[tm].x, af[tm].y, af[tm].z, af[tm].w, bf[tn].x, bf[tn].y);
        }
        if (more) STAGE_STORE(st ^ 1);
        __syncthreads();
    }
#undef STAGE_STORE

    int gid = lane >> 2, tg = lane & 3;
#pragma unroll
    for (int tm = 0; tm < 4; tm++) {
        int rr = m0 + wm * 64 + tm * 16 + gid;
        float b0v = bias[rr], b1v = bias[rr + 8];
#pragma unroll
        for (int tn = 0; tn < 4; tn++) {
            int cc = n0 + wn * 32 + tn * 8 + tg * 2;
            size_t o0 = (size_t)rr * N + cc;
            size_t o1 = (size_t)(rr + 8) * N + cc;
            float2 v0 = make_float2(acc[tm][tn][0] + b0v, acc[tm][tn][1] + b0v);
            float2 v1 = make_float2(acc[tm][tn][2] + b1v, acc[tm][tn][3] + b1v);
            if (PROJ) {
                float2 r0 = *(const float2*)&Rb[o0];
                float2 r1 = *(const float2*)&Rb[o1];
                v0.x += r0.x; v0.y += r0.y;
                v1.x += r1.x; v1.y += r1.y;
            }
            *(float2*)&Ob[o0] = v0;
            *(float2*)&Ob[o1] = v1;
        }
    }
}

// ---------------- tensor-core flash attention ----------------
// 128 threads = 4 warps; warp w owns Q rows [16w, 16w+16). 64-col K/V tiles.
// Smem (dynamic, 54KB): Qs[64][72], Ks[64][72] (overlaid by P-frags), Vs[64][72], tf32 bits.
#define SROW 72
__global__ __launch_bounds__(128, 4) void attn_kernel() {
    extern __shared__ unsigned sm[];
    unsigned* Qs = sm;                      // [d][r]
    unsigned* Ks = sm + 64 * SROW;          // [d][c]
    unsigned* Vs = sm + 2 * 64 * SROW;      // [d][c]
    unsigned* PA = Ks;                      // [ct8][w4][slot4][lane32]

    int q0 = blockIdx.x * 64;
    int h = blockIdx.y;
    int b = blockIdx.z;
    int tid = threadIdx.x, L = tid & 31, w = tid >> 5;
    const float scale = 0.35355339059327373f;

    const float* qp = g_qkv + ((size_t)b * 3 * Cc + (size_t)h * 3 * CHd) * Tt;
    const float* kp = qp + (size_t)CHd * Tt;
    const float* vp = qp + (size_t)2 * CHd * Tt;

    for (int idx = tid * 4; idx < 64 * 64; idx += 512) {
        int d = idx >> 6, r = idx & 63;
        float4 v = *(const float4*)&qp[(size_t)d * Tt + q0 + r];
        *(uint4*)&Qs[d * SROW + r] = make_uint4(f2tf(v.x * scale), f2tf(v.y * scale),
                                                f2tf(v.z * scale), f2tf(v.w * scale));
    }

    float o[8][4];
#pragma unroll
    for (int i = 0; i < 8; i++)
#pragma unroll
        for (int j = 0; j < 4; j++) o[i][j] = 0.f;
    float m0 = -3.0e38f, m1 = -3.0e38f, l0 = 0.f, l1 = 0.f;

    int r0 = L >> 2, r1 = r0 + 8;
    int cb = 2 * (L & 3);
    int k3 = L & 3;

    for (int k0 = 0; k0 < Tt; k0 += 64) {
        __syncthreads();   // Q staged (iter0) + prior readers of Ks/PA/Vs done
        for (int idx = tid * 4; idx < 64 * 64; idx += 512) {
            int d = idx >> 6, c = idx & 63;
            float4 kv = *(const float4*)&kp[(size_t)d * Tt + k0 + c];
            float4 vv = *(const float4*)&vp[(size_t)d * Tt + k0 + c];
            *(uint4*)&Ks[d * SROW + c] = make_uint4(f2tf(kv.x * scale), f2tf(kv.y * scale),
                                                    f2tf(kv.z * scale), f2tf(kv.w * scale));
            *(uint4*)&Vs[d * SROW + c] = make_uint4(f2tf(vv.x), f2tf(vv.y),
                                                    f2tf(vv.z), f2tf(vv.w));
        }
        __syncthreads();

        // ---- S = Q K^T ----
        float s[8][4];
#pragma unroll
        for (int i = 0; i < 8; i++)
#pragma unroll
            for (int j = 0; j < 4; j++) s[i][j] = 0.f;
#pragma unroll
        for (int dt = 0; dt < 8; dt++) {
            int dr = 8 * dt + k3;
            unsigned a0 = Qs[dr * SROW + 16 * w + r0];
            unsigned a1 = Qs[dr * SROW + 16 * w + r0 + 8];
            unsigned a2 = Qs[(dr + 4) * SROW + 16 * w + r0];
            unsigned a3 = Qs[(dr + 4) * SROW + 16 * w + r0 + 8];
#pragma unroll
            for (int nt = 0; nt < 8; nt++) {
                unsigned b0 = Ks[dr * SROW + 8 * nt + r0];
                unsigned b1 = Ks[(dr + 4) * SROW + 8 * nt + r0];
                MMA_TF32(s[nt][0], s[nt][1], s[nt][2], s[nt][3], a0, a1, a2, a3, b0, b1);
            }
        }

        // ---- bias + online softmax on C-fragments ----
        const float* tbp = g_tab + h * (2 * Tt - 1) + (Tt - 1) + q0 + 16 * w - k0;
        float tm0 = -3.0e38f, tm1 = -3.0e38f;
#pragma unroll
        for (int nt = 0; nt < 8; nt++) {
            int cc = 8 * nt + cb;
            s[nt][0] += tbp[r0 - cc];
            s[nt][1] += tbp[r0 - cc - 1];
            s[nt][2] += tbp[r1 - cc];
            s[nt][3] += tbp[r1 - cc - 1];
            tm0 = fmaxf(tm0, fmaxf(s[nt][0], s[nt][1]));
            tm1 = fmaxf(tm1, fmaxf(s[nt][2], s[nt][3]));
        }
        tm0 = fmaxf(tm0, __shfl_xor_sync(0xffffffffu, tm0, 1));
        tm0 = fmaxf(tm0, __shfl_xor_sync(0xffffffffu, tm0, 2));
        tm1 = fmaxf(tm1, __shfl_xor_sync(0xffffffffu, tm1, 1));
        tm1 = fmaxf(tm1, __shfl_xor_sync(0xffffffffu, tm1, 2));
        float mn0 = fmaxf(m0, tm0), mn1 = fmaxf(m1, tm1);
        float sc0 = __expf(m0 - mn0), sc1 = __expf(m1 - mn1);
        float rs0 = 0.f, rs1 = 0.f;
#pragma unroll
        for (int nt = 0; nt < 8; nt++) {
            s[nt][0] = __expf(s[nt][0] - mn0);
            s[nt][1] = __expf(s[nt][1] - mn0);
            s[nt][2] = __expf(s[nt][2] - mn1);
            s[nt][3] = __expf(s[nt][3] - mn1);
            rs0 += s[nt][0] + s[nt][1];
            rs1 += s[nt][2] + s[nt][3];
        }
        rs0 += __shfl_xor_sync(0xffffffffu, rs0, 1);
        rs0 += __shfl_xor_sync(0xffffffffu, rs0, 2);
        rs1 += __shfl_xor_sync(0xffffffffu, rs1, 1);
        rs1 += __shfl_xor_sync(0xffffffffu, rs1, 2);
        l0 = l0 * sc0 + rs0;
        l1 = l1 * sc1 + rs1;
        m0 = mn0; m1 = mn1;
#pragma unroll
        for (int nt = 0; nt < 8; nt++) {
            o[nt][0] *= sc0; o[nt][1] *= sc0;
            o[nt][2] *= sc1; o[nt][3] *= sc1;
        }

        // ---- P -> A-fragment smem (overlays Ks; per-warp private region) ----
        __syncthreads();   // all warps done reading Ks as K
        int sa = (cb >= 4) ? 2 : 0;
        int la = (r0 << 2) | (cb & 3);
#pragma unroll
        for (int nt = 0; nt < 8; nt++) {
            unsigned* pb = PA + ((nt * 4 + w) * 4) * 32;
            pb[sa * 32 + la]           = f2tf(s[nt][0]);
            pb[sa * 32 + la + 1]       = f2tf(s[nt][1]);
            pb[(sa + 1) * 32 + la]     = f2tf(s[nt][2]);
            pb[(sa + 1) * 32 + la + 1] = f2tf(s[nt][3]);
        }
        __syncwarp();

        // ---- O += P V ----
#pragma unroll
        for (int ct = 0; ct < 8; ct++) {
            const unsigned* pb = PA + ((ct * 4 + w) * 4) * 32;
            unsigned a0 = pb[L], a1 = pb[32 + L], a2 = pb[64 + L], a3 = pb[96 + L];
#pragma unroll
            for (int nt = 0; nt < 8; nt++) {
                unsigned b0 = Vs[(8 * nt + r0) * SROW + 8 * ct + k3];
                unsigned b1 = Vs[(8 * nt + r0) * SROW + 8 * ct + k3 + 4];
                MMA_TF32(o[nt][0], o[nt][1], o[nt][2], o[nt][3], a0, a1, a2, a3, b0, b1);
            }
        }
    }

    float il0 = 1.0f / l0, il1 = 1.0f / l1;
    size_t hb = (size_t)b * Cc + (size_t)h * CHd;
#pragma unroll
    for (int nt = 0; nt < 8; nt++) {
        int d = 8 * nt + cb;
        size_t base = (hb + d) * Tt + q0 + 16 * w;
        g_a[base + r0]      = o[nt][0] * il0;
        g_a[base + Tt + r0] = o[nt][1] * il0;
        g_a[base + r1]      = o[nt][2] * il1;
        g_a[base + Tt + r1] = o[nt][3] * il1;
    }
}

// ---------------- launch ----------------
extern "C" void kernel_launch(void* const* d_in, const int* in_sizes, int n_in,
                              void* d_out, int out_size) {
    const float* x       = (const float*)d_in[0];
    const float* gn_w    = (const float*)d_in[1];
    const float* gn_b    = (const float*)d_in[2];
    const float* qkv_w   = (const float*)d_in[3];
    const float* qkv_b   = (const float*)d_in[4];
    const float* proj_w  = (const float*)d_in[5];
    const float* proj_b  = (const float*)d_in[6];
    const float* rel_emb = (const float*)d_in[7];
    float* out = (float*)d_out;
    (void)in_sizes; (void)n_in; (void)out_size;

    const int attn_smem = 3 * 64 * SROW * 4;   // 55296 B
    cudaFuncSetAttribute(attn_kernel, cudaFuncAttributeMaxDynamicSharedMemorySize, attn_smem);

    fill_tab_kernel<<<(Hh * (2 * Tt - 1) + 255) / 256, 256>>>(rel_emb);
    gn_kernel<<<Bq * Gg, 256>>>(x, gn_w, gn_b);
    mma_gemm<false><<<dim3(Tt / 128, (3 * Cc) / 128, Bq), 256>>>(qkv_w, qkv_b, nullptr, nullptr);
    attn_kernel<<<dim3(Tt / 64, Hh, Bq), 128, attn_smem>>>();
    mma_gemm<true><<<dim3(Tt / 128, Cc / 128, Bq), 256>>>(proj_w, proj_b, x, out);
}

// round 5
// speedup vs baseline: 2.8474x; 1.6015x over previous
#include <cuda_runtime.h>
#include <math.h>
#include <stdint.h>

#define Bq 2
#define Cc 1024
#define Tt 2048
#define Hh 16
#define CHd 64
#define Gg 32

// ---------------- scratch (device globals; no allocations) ----------------
__device__ float g_xn[(size_t)Bq * Cc * Tt];
__device__ float g_qkv[(size_t)Bq * 3 * Cc * Tt];
__device__ float g_a[(size_t)Bq * Cc * Tt];
__device__ float g_tab[Hh * (2 * Tt - 1)];

// ---------------- relative-position bias table ----------------
__global__ void fill_tab_kernel(const float* __restrict__ rel_emb) {
    int idx = blockIdx.x * 256 + threadIdx.x;
    const int NT = Hh * (2 * Tt - 1);
    if (idx >= NT) return;
    int h = idx / (2 * Tt - 1);
    int di = idx % (2 * Tt - 1);
    int n = di - (Tt - 1);            // n = q - k
    int ret = 0;
    if (n < 0) { ret = 16; n = -n; }
    int bucket;
    if (n < 8) {
        bucket = ret + n;
    } else {
        float v = logf((float)n * 0.125f) / logf(8.0f) * 8.0f;
        int vi = 8 + (int)v;
        if (vi > 15) vi = 15;
        bucket = ret + vi;
    }
    g_tab[h * (2 * Tt - 1) + di] = rel_emb[bucket * Hh + h] * 8.0f;
}

// ---------------- GroupNorm ----------------
__global__ __launch_bounds__(256) void gn_kernel(const float* __restrict__ x,
                                                 const float* __restrict__ w,
                                                 const float* __restrict__ bb) {
    int blk = blockIdx.x;
    int b = blk >> 5, g = blk & 31;
    const int CPG = Cc / Gg;
    const int NE = CPG * Tt;
    const float* xp = x + ((size_t)b * Cc + (size_t)g * CPG) * Tt;
    float* op = g_xn + ((size_t)b * Cc + (size_t)g * CPG) * Tt;
    int tid = threadIdx.x;

    float s = 0.f, s2 = 0.f;
    for (int i = tid; i < NE; i += 256) {
        float v = xp[i];
        s += v;
        s2 = fmaf(v, v, s2);
    }
    for (int o = 16; o; o >>= 1) {
        s  += __shfl_xor_sync(0xffffffffu, s, o);
        s2 += __shfl_xor_sync(0xffffffffu, s2, o);
    }
    __shared__ float sh[2][8];
    int wid = tid >> 5, ln = tid & 31;
    if (ln == 0) { sh[0][wid] = s; sh[1][wid] = s2; }
    __syncthreads();
    if (tid == 0) {
        float a = 0.f, c = 0.f;
        for (int i = 0; i < 8; i++) { a += sh[0][i]; c += sh[1][i]; }
        float mu = a / (float)NE;
        float var = c / (float)NE - mu * mu;
        sh[0][0] = mu;
        sh[1][0] = rsqrtf(var + 1e-5f);
    }
    __syncthreads();
    float mu = sh[0][0], inv = sh[1][0];
    for (int i = tid; i < NE; i += 256) {
        int c = g * CPG + i / Tt;
        op[i] = (xp[i] - mu) * inv * w[c] + bb[c];
    }
}

// MMA on raw fp32 operands: HW truncates to tf32 internally.
#define MMA_F(C, A0, A1, A2, A3, B0, B1) \
    asm volatile("mma.sync.aligned.m16n8k8.row.col.f32.tf32.tf32.f32 " \
                 "{%0,%1,%2,%3}, {%4,%5,%6,%7}, {%8,%9}, {%0,%1,%2,%3};" \
                 : "+f"((C)[0]), "+f"((C)[1]), "+f"((C)[2]), "+f"((C)[3]) \
                 : "r"(__float_as_uint(A0)), "r"(__float_as_uint(A1)), \
                   "r"(__float_as_uint(A2)), "r"(__float_as_uint(A3)), \
                   "r"(__float_as_uint(B0)), "r"(__float_as_uint(B1)))

__device__ __forceinline__ void cp16(uint32_t dst, const void* src) {
    asm volatile("cp.async.cg.shared.global [%0], [%1], 16;" :: "r"(dst), "l"(src));
}
#define CP_COMMIT() asm volatile("cp.async.commit_group;" ::: "memory")
#define CP_WAIT3()  asm volatile("cp.async.wait_group 3;" ::: "memory")

// ---------------- tf32 GEMM: cp.async 5-stage pipeline, conflict-free padded smem ----
// out[m][n] = sum_k W[m][k] X[k][n] + bias[m] (+resid). Block 128x128, BK=16, 8 warps.
#define GSTG 5
#define AW 20                 // A row stride (16 + 4 pad) words
#define BW 136                // B row stride (128 + 8 pad) words
#define AST (128 * AW)        // 2560 words / stage
#define BST (16 * BW)         // 2176 words / stage
#define GEMM_SMEM (GSTG * (AST + BST) * 4)

template <bool PROJ>
__global__ __launch_bounds__(256, 2) void mma_gemm(const float* __restrict__ Wt,
                                                   const float* __restrict__ bias,
                                                   const float* __restrict__ resid,
                                                   float* __restrict__ outp) {
    const int N = Tt, K = Cc;
    int b = blockIdx.z;
    const float* Xb = (PROJ ? g_a : g_xn) + (size_t)b * Cc * Tt;
    float* Ob = PROJ ? (outp + (size_t)b * Cc * Tt) : (g_qkv + (size_t)b * 3 * Cc * Tt);
    const float* Rb = PROJ ? (resid + (size_t)b * Cc * Tt) : nullptr;

    extern __shared__ float gs[];
    float* As = gs;
    float* Bs = gs + GSTG * AST;
    uint32_t as_u = (uint32_t)__cvta_generic_to_shared(As);
    uint32_t bs_u = (uint32_t)__cvta_generic_to_shared(Bs);

    int m0 = blockIdx.y * 128, n0 = blockIdx.x * 128;
    int tid = threadIdx.x, lane = tid & 31, warp = tid >> 5;
    int wm = warp & 1, wn = warp >> 1;
    int g = lane >> 2, t = lane & 3;

    // cp.async chunk coords
    int arow = tid >> 2, akq = (tid & 3) * 4;        // A: rows arow, arow+64
    int brow = tid >> 5, bnc = (tid & 31) * 4;       // B: rows brow, brow+8
    const float* aSrc = Wt + (size_t)(m0 + arow) * K + akq;
    const float* bSrc = Xb + (size_t)brow * N + n0 + bnc;
    uint32_t aDst = as_u + (arow * AW + akq) * 4;
    uint32_t bDst = bs_u + (brow * BW + bnc) * 4;

    float acc[4][4][4];
#pragma unroll
    for (int i = 0; i < 4; i++)
#pragma unroll
        for (int j = 0; j < 4; j++)
#pragma unroll
            for (int q = 0; q < 4; q++) acc[i][j][q] = 0.f;

    const int NK = K / 16;   // 64

#define G_ISSUE(ST, KT) do { \
    cp16(aDst + (ST) * AST * 4, aSrc + (KT)); \
    cp16(aDst + ((ST) * AST + 64 * AW) * 4, aSrc + (size_t)64 * K + (KT)); \
    cp16(bDst + (ST) * BST * 4, bSrc + (size_t)(KT) * N); \
    cp16(bDst + ((ST) * BST + 8 * BW) * 4, bSrc + (size_t)(KT + 8) * N); \
} while (0)

#pragma unroll
    for (int s = 0; s < 4; s++) {
        G_ISSUE(s, s * 16);
        CP_COMMIT();
    }

    for (int i = 0; i < NK; i++) {
        int st = i % GSTG;
        CP_WAIT3();
        __syncthreads();
        if (i + 4 < NK) {
            int ns = (i + 4) % GSTG;
            G_ISSUE(ns, (i + 4) * 16);
        }
        CP_COMMIT();

        const float* A0 = As + st * AST + (size_t)wm * 64 * AW;
        const float* B0 = Bs + st * BST + wn * 32;
#pragma unroll
        for (int kk = 0; kk < 16; kk += 8) {
            float af[4][4];
            float bf[4][2];
#pragma unroll
            for (int mt = 0; mt < 4; mt++) {
                const float* ap = A0 + (mt * 16 + g) * AW + kk + t;
                af[mt][0] = ap[0];
                af[mt][1] = ap[8 * AW];
                af[mt][2] = ap[4];
                af[mt][3] = ap[8 * AW + 4];
            }
#pragma unroll
            for (int nt = 0; nt < 4; nt++) {
                const float* bp = B0 + (kk + t) * BW + nt * 8 + g;
                bf[nt][0] = bp[0];
                bf[nt][1] = bp[4 * BW];
            }
#pragma unroll
            for (int mt = 0; mt < 4; mt++)
#pragma unroll
                for (int nt = 0; nt < 4; nt++)
                    MMA_F(acc[mt][nt], af[mt][0], af[mt][1], af[mt][2], af[mt][3],
                          bf[nt][0], bf[nt][1]);
        }
    }
#undef G_ISSUE

    int gid = lane >> 2, tg = lane & 3;
#pragma unroll
    for (int tm = 0; tm < 4; tm++) {
        int rr = m0 + wm * 64 + tm * 16 + gid;
        float b0v = bias[rr], b1v = bias[rr + 8];
#pragma unroll
        for (int tn = 0; tn < 4; tn++) {
            int cc = n0 + wn * 32 + tn * 8 + tg * 2;
            size_t o0 = (size_t)rr * N + cc;
            size_t o1 = (size_t)(rr + 8) * N + cc;
            float2 v0 = make_float2(acc[tm][tn][0] + b0v, acc[tm][tn][1] + b0v);
            float2 v1 = make_float2(acc[tm][tn][2] + b1v, acc[tm][tn][3] + b1v);
            if (PROJ) {
                float2 r0 = *(const float2*)&Rb[o0];
                float2 r1 = *(const float2*)&Rb[o1];
                v0.x += r0.x; v0.y += r0.y;
                v1.x += r1.x; v1.y += r1.y;
            }
            *(float2*)&Ob[o0] = v0;
            *(float2*)&Ob[o1] = v1;
        }
    }
}

// ---------------- tensor-core flash attention (Q=128, 8 warps, P via shuffles) -------
#define QW 136
#define KW 72
#define ATTN_SMEM ((64 * QW + 2 * 64 * KW) * 4)
__global__ __launch_bounds__(256, 2) void attn_kernel() {
    extern __shared__ float sm[];
    float* Qs = sm;                  // [d 64][r 128 + pad]
    float* Ks = sm + 64 * QW;        // [d 64][c 64 + pad]
    float* Vs = Ks + 64 * KW;        // [d 64][c 64 + pad]

    int q0 = blockIdx.x * 128;
    int h = blockIdx.y;
    int b = blockIdx.z;
    int tid = threadIdx.x, L = tid & 31, w = tid >> 5;
    const float scale = 0.35355339059327373f;

    const float* qp = g_qkv + ((size_t)b * 3 * Cc + (size_t)h * 3 * CHd) * Tt;
    const float* kp = qp + (size_t)CHd * Tt;
    const float* vp = qp + (size_t)2 * CHd * Tt;

    for (int idx = tid * 4; idx < 64 * 128; idx += 1024) {
        int d = idx >> 7, r = idx & 127;
        float4 v = *(const float4*)&qp[(size_t)d * Tt + q0 + r];
        v.x *= scale; v.y *= scale; v.z *= scale; v.w *= scale;
        *(float4*)&Qs[d * QW + r] = v;
    }

    float o[8][4];
#pragma unroll
    for (int i = 0; i < 8; i++)
#pragma unroll
        for (int j = 0; j < 4; j++) o[i][j] = 0.f;
    float m0 = -3.0e38f, m1 = -3.0e38f, l0 = 0.f, l1 = 0.f;

    int g = L >> 2, t = L & 3;
    int cb = 2 * t;
    int sidx = (L & 28) | (t >> 1);     // shuffle source lane for P transpose

    const float* tb = g_tab + h * (2 * Tt - 1) + (Tt - 1) + q0 + 16 * w;

    for (int k0 = 0; k0 < Tt; k0 += 64) {
        __syncthreads();
        for (int idx = tid * 4; idx < 4096; idx += 1024) {
            int d = idx >> 6, c = idx & 63;
            float4 kv = *(const float4*)&kp[(size_t)d * Tt + k0 + c];
            kv.x *= scale; kv.y *= scale; kv.z *= scale; kv.w *= scale;
            *(float4*)&Ks[d * KW + c] = kv;
            *(float4*)&Vs[d * KW + c] = *(const float4*)&vp[(size_t)d * Tt + k0 + c];
        }
        __syncthreads();

        // ---- S = Q K^T ----
        float s[8][4];
#pragma unroll
        for (int i = 0; i < 8; i++)
#pragma unroll
            for (int j = 0; j < 4; j++) s[i][j] = 0.f;
#pragma unroll
        for (int dt = 0; dt < 8; dt++) {
            const float* qb = &Qs[(8 * dt + t) * QW + 16 * w + g];
            float a0 = qb[0], a1 = qb[8], a2 = qb[4 * QW], a3 = qb[4 * QW + 8];
            const float* kb = &Ks[(8 * dt + t) * KW + g];
#pragma unroll
            for (int nt = 0; nt < 8; nt++)
                MMA_F(s[nt], a0, a1, a2, a3, kb[8 * nt], kb[4 * KW + 8 * nt]);
        }

        // ---- bias + online softmax ----
        const float* tbp = tb - k0;
        float tm0 = -3.0e38f, tm1 = -3.0e38f;
#pragma unroll
        for (int nt = 0; nt < 8; nt++) {
            int cc = 8 * nt + cb;
            s[nt][0] += tbp[g - cc];
            s[nt][1] += tbp[g - cc - 1];
            s[nt][2] += tbp[g + 8 - cc];
            s[nt][3] += tbp[g + 8 - cc - 1];
            tm0 = fmaxf(tm0, fmaxf(s[nt][0], s[nt][1]));
            tm1 = fmaxf(tm1, fmaxf(s[nt][2], s[nt][3]));
        }
        tm0 = fmaxf(tm0, __shfl_xor_sync(0xffffffffu, tm0, 1));
        tm0 = fmaxf(tm0, __shfl_xor_sync(0xffffffffu, tm0, 2));
        tm1 = fmaxf(tm1, __shfl_xor_sync(0xffffffffu, tm1, 1));
        tm1 = fmaxf(tm1, __shfl_xor_sync(0xffffffffu, tm1, 2));
        float mn0 = fmaxf(m0, tm0), mn1 = fmaxf(m1, tm1);
        float sc0 = __expf(m0 - mn0), sc1 = __expf(m1 - mn1);
        float rs0 = 0.f, rs1 = 0.f;
#pragma unroll
        for (int nt = 0; nt < 8; nt++) {
            s[nt][0] = __expf(s[nt][0] - mn0);
            s[nt][1] = __expf(s[nt][1] - mn0);
            s[nt][2] = __expf(s[nt][2] - mn1);
            s[nt][3] = __expf(s[nt][3] - mn1);
            rs0 += s[nt][0] + s[nt][1];
            rs1 += s[nt][2] + s[nt][3];
        }
        rs0 += __shfl_xor_sync(0xffffffffu, rs0, 1);
        rs0 += __shfl_xor_sync(0xffffffffu, rs0, 2);
        rs1 += __shfl_xor_sync(0xffffffffu, rs1, 1);
        rs1 += __shfl_xor_sync(0xffffffffu, rs1, 2);
        l0 = l0 * sc0 + rs0;
        l1 = l1 * sc1 + rs1;
        m0 = mn0; m1 = mn1;
#pragma unroll
        for (int nt = 0; nt < 8; nt++) {
            o[nt][0] *= sc0; o[nt][1] *= sc0;
            o[nt][2] *= sc1; o[nt][3] *= sc1;
        }

        // ---- O += P V :  P C-frag -> A-frag via shuffles (no smem round-trip) ----
#pragma unroll
        for (int ct = 0; ct < 8; ct++) {
            float v00 = __shfl_sync(0xffffffffu, s[ct][0], sidx);
            float v01 = __shfl_sync(0xffffffffu, s[ct][1], sidx);
            float v10 = __shfl_sync(0xffffffffu, s[ct][2], sidx);
            float v11 = __shfl_sync(0xffffffffu, s[ct][3], sidx);
            float w00 = __shfl_sync(0xffffffffu, s[ct][0], sidx + 2);
            float w01 = __shfl_sync(0xffffffffu, s[ct][1], sidx + 2);
            float w10 = __shfl_sync(0xffffffffu, s[ct][2], sidx + 2);
            float w11 = __shfl_sync(0xffffffffu, s[ct][3], sidx + 2);
            float pa0 = (t & 1) ? v01 : v00;
            float pa1 = (t & 1) ? v11 : v10;
            float pa2 = (t & 1) ? w01 : w00;
            float pa3 = (t & 1) ? w11 : w10;
            const float* vb = &Vs[g * KW + 8 * ct + t];
#pragma unroll
            for (int nt = 0; nt < 8; nt++)
                MMA_F(o[nt], pa0, pa1, pa2, pa3,
                      vb[8 * nt * KW], vb[8 * nt * KW + 4]);
        }
    }

    float il0 = 1.0f / l0, il1 = 1.0f / l1;
    size_t hb = (size_t)b * Cc + (size_t)h * CHd;
#pragma unroll
    for (int nt = 0; nt < 8; nt++) {
        int d = 8 * nt + cb;
        size_t base = (hb + d) * Tt + q0 + 16 * w;
        g_a[base + g]          = o[nt][0] * il0;
        g_a[base + Tt + g]     = o[nt][1] * il0;
        g_a[base + g + 8]      = o[nt][2] * il1;
        g_a[base + Tt + g + 8] = o[nt][3] * il1;
    }
}

// ---------------- launch ----------------
extern "C" void kernel_launch(void* const* d_in, const int* in_sizes, int n_in,
                              void* d_out, int out_size) {
    const float* x       = (const float*)d_in[0];
    const float* gn_w    = (const float*)d_in[1];
    const float* gn_b    = (const float*)d_in[2];
    const float* qkv_w   = (const float*)d_in[3];
    const float* qkv_b   = (const float*)d_in[4];
    const float* proj_w  = (const float*)d_in[5];
    const float* proj_b  = (const float*)d_in[6];
    const float* rel_emb = (const float*)d_in[7];
    float* out = (float*)d_out;
    (void)in_sizes; (void)n_in; (void)out_size;

    cudaFuncSetAttribute(mma_gemm<false>, cudaFuncAttributeMaxDynamicSharedMemorySize, GEMM_SMEM);
    cudaFuncSetAttribute(mma_gemm<true>,  cudaFuncAttributeMaxDynamicSharedMemorySize, GEMM_SMEM);
    cudaFuncSetAttribute(attn_kernel, cudaFuncAttributeMaxDynamicSharedMemorySize, ATTN_SMEM);

    fill_tab_kernel<<<(Hh * (2 * Tt - 1) + 255) / 256, 256>>>(rel_emb);
    gn_kernel<<<Bq * Gg, 256>>>(x, gn_w, gn_b);
    mma_gemm<false><<<dim3(Tt / 128, (3 * Cc) / 128, Bq), 256, GEMM_SMEM>>>(qkv_w, qkv_b, nullptr, nullptr);
    attn_kernel<<<dim3(Tt / 128, Hh, Bq), 256, ATTN_SMEM>>>();
    mma_gemm<true><<<dim3(Tt / 128, Cc / 128, Bq), 256, GEMM_SMEM>>>(proj_w, proj_b, x, out);
}

// round 7
// speedup vs baseline: 3.4151x; 1.1994x over previous
#include <cuda_runtime.h>
#include <math.h>
#include <stdint.h>

#define Bq 2
#define Cc 1024
#define Tt 2048
#define Hh 16
#define CHd 64
#define Gg 32

// ---------------- scratch (device globals; no allocations) ----------------
__device__ float g_xn[(size_t)Bq * Cc * Tt];
__device__ float g_qkv[(size_t)Bq * 3 * Cc * Tt];
__device__ float g_a[(size_t)Bq * Cc * Tt];
__device__ float g_tab[Hh * (2 * Tt - 1)];

// ---------------- relative-position bias table ----------------
__global__ void fill_tab_kernel(const float* __restrict__ rel_emb) {
    int idx = blockIdx.x * 256 + threadIdx.x;
    const int NT = Hh * (2 * Tt - 1);
    if (idx >= NT) return;
    int h = idx / (2 * Tt - 1);
    int di = idx % (2 * Tt - 1);
    int n = di - (Tt - 1);            // n = q - k
    int ret = 0;
    if (n < 0) { ret = 16; n = -n; }
    int bucket;
    if (n < 8) {
        bucket = ret + n;
    } else {
        float v = logf((float)n * 0.125f) / logf(8.0f) * 8.0f;
        int vi = 8 + (int)v;
        if (vi > 15) vi = 15;
        bucket = ret + vi;
    }
    g_tab[h * (2 * Tt - 1) + di] = rel_emb[bucket * Hh + h] * 8.0f;
}

// ---------------- GroupNorm ----------------
__global__ __launch_bounds__(256) void gn_kernel(const float* __restrict__ x,
                                                 const float* __restrict__ w,
                                                 const float* __restrict__ bb) {
    int blk = blockIdx.x;
    int b = blk >> 5, g = blk & 31;
    const int CPG = Cc / Gg;
    const int NE = CPG * Tt;
    const float* xp = x + ((size_t)b * Cc + (size_t)g * CPG) * Tt;
    float* op = g_xn + ((size_t)b * Cc + (size_t)g * CPG) * Tt;
    int tid = threadIdx.x;

    float s = 0.f, s2 = 0.f;
    for (int i = tid; i < NE; i += 256) {
        float v = xp[i];
        s += v;
        s2 = fmaf(v, v, s2);
    }
    for (int o = 16; o; o >>= 1) {
        s  += __shfl_xor_sync(0xffffffffu, s, o);
        s2 += __shfl_xor_sync(0xffffffffu, s2, o);
    }
    __shared__ float sh[2][8];
    int wid = tid >> 5, ln = tid & 31;
    if (ln == 0) { sh[0][wid] = s; sh[1][wid] = s2; }
    __syncthreads();
    if (tid == 0) {
        float a = 0.f, c = 0.f;
        for (int i = 0; i < 8; i++) { a += sh[0][i]; c += sh[1][i]; }
        float mu = a / (float)NE;
        float var = c / (float)NE - mu * mu;
        sh[0][0] = mu;
        sh[1][0] = rsqrtf(var + 1e-5f);
    }
    __syncthreads();
    float mu = sh[0][0], inv = sh[1][0];
    for (int i = tid; i < NE; i += 256) {
        int c = g * CPG + i / Tt;
        op[i] = (xp[i] - mu) * inv * w[c] + bb[c];
    }
}

// MMA on raw fp32 operands: HW truncates to tf32 internally.
#define MMA_F(C, A0, A1, A2, A3, B0, B1) \
    asm volatile("mma.sync.aligned.m16n8k8.row.col.f32.tf32.tf32.f32 " \
                 "{%0,%1,%2,%3}, {%4,%5,%6,%7}, {%8,%9}, {%0,%1,%2,%3};" \
                 : "+f"((C)[0]), "+f"((C)[1]), "+f"((C)[2]), "+f"((C)[3]) \
                 : "r"(__float_as_uint(A0)), "r"(__float_as_uint(A1)), \
                   "r"(__float_as_uint(A2)), "r"(__float_as_uint(A3)), \
                   "r"(__float_as_uint(B0)), "r"(__float_as_uint(B1)))

__device__ __forceinline__ void cp16(uint32_t dst, const void* src) {
    asm volatile("cp.async.cg.shared.global [%0], [%1], 16;" :: "r"(dst), "l"(src));
}
#define CP_COMMIT() asm volatile("cp.async.commit_group;" ::: "memory")
#define CP_WAIT3()  asm volatile("cp.async.wait_group 3;" ::: "memory")
#define CP_WAIT1()  asm volatile("cp.async.wait_group 1;" ::: "memory")

// ---------------- tf32 GEMM: cp.async 5-stage pipeline (unchanged from R4) ----------
#define GSTG 5
#define AW 20
#define BW 136
#define AST (128 * AW)
#define BST (16 * BW)
#define GEMM_SMEM (GSTG * (AST + BST) * 4)

template <bool PROJ>
__global__ __launch_bounds__(256, 2) void mma_gemm(const float* __restrict__ Wt,
                                                   const float* __restrict__ bias,
                                                   const float* __restrict__ resid,
                                                   float* __restrict__ outp) {
    const int N = Tt, K = Cc;
    int b = blockIdx.z;
    const float* Xb = (PROJ ? g_a : g_xn) + (size_t)b * Cc * Tt;
    float* Ob = PROJ ? (outp + (size_t)b * Cc * Tt) : (g_qkv + (size_t)b * 3 * Cc * Tt);
    const float* Rb = PROJ ? (resid + (size_t)b * Cc * Tt) : nullptr;

    extern __shared__ float gs[];
    float* As = gs;
    float* Bs = gs + GSTG * AST;
    uint32_t as_u = (uint32_t)__cvta_generic_to_shared(As);
    uint32_t bs_u = (uint32_t)__cvta_generic_to_shared(Bs);

    int m0 = blockIdx.y * 128, n0 = blockIdx.x * 128;
    int tid = threadIdx.x, lane = tid & 31, warp = tid >> 5;
    int wm = warp & 1, wn = warp >> 1;
    int g = lane >> 2, t = lane & 3;

    int arow = tid >> 2, akq = (tid & 3) * 4;
    int brow = tid >> 5, bnc = (tid & 31) * 4;
    const float* aSrc = Wt + (size_t)(m0 + arow) * K + akq;
    const float* bSrc = Xb + (size_t)brow * N + n0 + bnc;
    uint32_t aDst = as_u + (arow * AW + akq) * 4;
    uint32_t bDst = bs_u + (brow * BW + bnc) * 4;

    float acc[4][4][4];
#pragma unroll
    for (int i = 0; i < 4; i++)
#pragma unroll
        for (int j = 0; j < 4; j++)
#pragma unroll
            for (int q = 0; q < 4; q++) acc[i][j][q] = 0.f;

    const int NK = K / 16;

#define G_ISSUE(ST, KT) do { \
    cp16(aDst + (ST) * AST * 4, aSrc + (KT)); \
    cp16(aDst + ((ST) * AST + 64 * AW) * 4, aSrc + (size_t)64 * K + (KT)); \
    cp16(bDst + (ST) * BST * 4, bSrc + (size_t)(KT) * N); \
    cp16(bDst + ((ST) * BST + 8 * BW) * 4, bSrc + (size_t)(KT + 8) * N); \
} while (0)

#pragma unroll
    for (int s = 0; s < 4; s++) {
        G_ISSUE(s, s * 16);
        CP_COMMIT();
    }

    for (int i = 0; i < NK; i++) {
        int st = i % GSTG;
        CP_WAIT3();
        __syncthreads();
        if (i + 4 < NK) {
            int ns = (i + 4) % GSTG;
            G_ISSUE(ns, (i + 4) * 16);
        }
        CP_COMMIT();

        const float* A0 = As + st * AST + (size_t)wm * 64 * AW;
        const float* B0 = Bs + st * BST + wn * 32;
#pragma unroll
        for (int kk = 0; kk < 16; kk += 8) {
            float af[4][4];
            float bf[4][2];
#pragma unroll
            for (int mt = 0; mt < 4; mt++) {
                const float* ap = A0 + (mt * 16 + g) * AW + kk + t;
                af[mt][0] = ap[0];
                af[mt][1] = ap[8 * AW];
                af[mt][2] = ap[4];
                af[mt][3] = ap[8 * AW + 4];
            }
#pragma unroll
            for (int nt = 0; nt < 4; nt++) {
                const float* bp = B0 + (kk + t) * BW + nt * 8 + g;
                bf[nt][0] = bp[0];
                bf[nt][1] = bp[4 * BW];
            }
#pragma unroll
            for (int mt = 0; mt < 4; mt++)
#pragma unroll
                for (int nt = 0; nt < 4; nt++)
                    MMA_F(acc[mt][nt], af[mt][0], af[mt][1], af[mt][2], af[mt][3],
                          bf[nt][0], bf[nt][1]);
        }
    }
#undef G_ISSUE

    int gid = lane >> 2, tg = lane & 3;
#pragma unroll
    for (int tm = 0; tm < 4; tm++) {
        int rr = m0 + wm * 64 + tm * 16 + gid;
        float b0v = bias[rr], b1v = bias[rr + 8];
#pragma unroll
        for (int tn = 0; tn < 4; tn++) {
            int cc = n0 + wn * 32 + tn * 8 + tg * 2;
            size_t o0 = (size_t)rr * N + cc;
            size_t o1 = (size_t)(rr + 8) * N + cc;
            float2 v0 = make_float2(acc[tm][tn][0] + b0v, acc[tm][tn][1] + b0v);
            float2 v1 = make_float2(acc[tm][tn][2] + b1v, acc[tm][tn][3] + b1v);
            if (PROJ) {
                float2 r0 = *(const float2*)&Rb[o0];
                float2 r1 = *(const float2*)&Rb[o1];
                v0.x += r0.x; v0.y += r0.y;
                v1.x += r1.x; v1.y += r1.y;
            }
            *(float2*)&Ob[o0] = v0;
            *(float2*)&Ob[o1] = v1;
        }
    }
}

// ---------------- flash attention: Q=128, 4 warps x m=32, cp.async double-buffer ----
// K/V smem [d 64][c 64] pad stride 72, 2 stages. Q [d 64][r 128] stride 136.
// Scale folded as scale^2 = 1/8 into Q staging only.
#define QW 136
#define KW 72
#define KVST (64 * KW)                       // words per K or V stage
#define ATTN_SMEM ((64 * QW + 4 * KVST) * 4) // 106496 B
__global__ __launch_bounds__(128, 2) void attn_kernel() {
    extern __shared__ float sm[];
    float* Qs = sm;                          // [d][r]
    float* KV = sm + 64 * QW;                // [stage][{K,V}][d][c]
    uint32_t kv_u = (uint32_t)__cvta_generic_to_shared(KV);

    int q0 = blockIdx.x * 128;
    int h = blockIdx.y;
    int b = blockIdx.z;
    int tid = threadIdx.x, L = tid & 31, w = tid >> 5;

    const float* qp = g_qkv + ((size_t)b * 3 * Cc + (size_t)h * 3 * CHd) * Tt;
    const float* kp = qp + (size_t)CHd * Tt;
    const float* vp = qp + (size_t)2 * CHd * Tt;

#define KV_ISSUE(ST, K0) do { \
    _Pragma("unroll") \
    for (int ch = 0; ch < 8; ch++) { \
        int cid = ch * 128 + tid; \
        int d = cid >> 4, c4 = (cid & 15) * 4; \
        cp16(kv_u + ((ST) * 2 * KVST + d * KW + c4) * 4, kp + (size_t)d * Tt + (K0) + c4); \
        cp16(kv_u + (((ST) * 2 + 1) * KVST + d * KW + c4) * 4, vp + (size_t)d * Tt + (K0) + c4); \
    } \
} while (0)

    KV_ISSUE(0, 0);
    CP_COMMIT();

    const float qsc = 0.125f;   // scale^2 = 1/sqrt(64)
    for (int idx = tid * 4; idx < 64 * 128; idx += 512) {
        int d = idx >> 7, r = idx & 127;
        float4 v = *(const float4*)&qp[(size_t)d * Tt + q0 + r];
        v.x *= qsc; v.y *= qsc; v.z *= qsc; v.w *= qsc;
        *(float4*)&Qs[d * QW + r] = v;
    }

    float o[2][8][4];
    float mx[2][2], lsum[2][2];
#pragma unroll
    for (int mt = 0; mt < 2; mt++) {
        mx[mt][0] = mx[mt][1] = -3.0e38f;
        lsum[mt][0] = lsum[mt][1] = 0.f;
#pragma unroll
        for (int i = 0; i < 8; i++)
#pragma unroll
            for (int j = 0; j < 4; j++) o[mt][i][j] = 0.f;
    }

    int g = L >> 2, t = L & 3;
    int cb = 2 * t;
    int sidx = (L & 28) | (t >> 1);

    const float* tb = g_tab + h * (2 * Tt - 1) + (Tt - 1) + q0 + 32 * w;

    const int NI = Tt / 64;
    for (int i = 0; i < NI; i++) {
        int st = i & 1;
        if (i > 0) __syncthreads();            // prior compute done with buffer st^1
        if (i + 1 < NI) KV_ISSUE(st ^ 1, (i + 1) * 64);
        CP_COMMIT();
        CP_WAIT1();                            // buffer st ready (this thread)
        __syncthreads();                       // visible block-wide

        const float* Ks = KV + st * 2 * KVST;
        const float* Vs = Ks + KVST;

        // ---- S = Q K^T  (K-frag reused across 2 m-tiles) ----
        float s[2][8][4];
#pragma unroll
        for (int mt = 0; mt < 2; mt++)
#pragma unroll
            for (int nt = 0; nt < 8; nt++)
#pragma unroll
                for (int j = 0; j < 4; j++) s[mt][nt][j] = 0.f;
#pragma unroll
        for (int dt = 0; dt < 8; dt++) {
            const float* q0p = &Qs[(8 * dt + t) * QW + 32 * w + g];
            float a[2][4];
#pragma unroll
            for (int mt = 0; mt < 2; mt++) {
                a[mt][0] = q0p[16 * mt];
                a[mt][1] = q0p[16 * mt + 8];
                a[mt][2] = q0p[4 * QW + 16 * mt];
                a[mt][3] = q0p[4 * QW + 16 * mt + 8];
            }
            const float* kb = &Ks[(8 * dt + t) * KW + g];
#pragma unroll
            for (int nt = 0; nt < 8; nt++) {
                float b0 = kb[8 * nt], b1 = kb[4 * KW + 8 * nt];
                MMA_F(s[0][nt], a[0][0], a[0][1], a[0][2], a[0][3], b0, b1);
                MMA_F(s[1][nt], a[1][0], a[1][1], a[1][2], a[1][3], b0, b1);
            }
        }

        // ---- bias + online softmax per m-tile ----
        const float* tbp = tb - i * 64;
#pragma unroll
        for (int mt = 0; mt < 2; mt++) {
            const float* tq = tbp + 16 * mt;
            float tm0 = -3.0e38f, tm1 = -3.0e38f;
#pragma unroll
            for (int nt = 0; nt < 8; nt++) {
                int cc = 8 * nt + cb;
                s[mt][nt][0] += tq[g - cc];
                s[mt][nt][1] += tq[g - cc - 1];
                s[mt][nt][2] += tq[g + 8 - cc];
                s[mt][nt][3] += tq[g + 8 - cc - 1];
                tm0 = fmaxf(tm0, fmaxf(s[mt][nt][0], s[mt][nt][1]));
                tm1 = fmaxf(tm1, fmaxf(s[mt][nt][2], s[mt][nt][3]));
            }
            tm0 = fmaxf(tm0, __shfl_xor_sync(0xffffffffu, tm0, 1));
            tm0 = fmaxf(tm0, __shfl_xor_sync(0xffffffffu, tm0, 2));
            tm1 = fmaxf(tm1, __shfl_xor_sync(0xffffffffu, tm1, 1));
            tm1 = fmaxf(tm1, __shfl_xor_sync(0xffffffffu, tm1, 2));
            float mn0 = fmaxf(mx[mt][0], tm0), mn1 = fmaxf(mx[mt][1], tm1);
            float sc0 = __expf(mx[mt][0] - mn0), sc1 = __expf(mx[mt][1] - mn1);
            float rs0 = 0.f, rs1 = 0.f;
#pragma unroll
            for (int nt = 0; nt < 8; nt++) {
                s[mt][nt][0] = __expf(s[mt][nt][0] - mn0);
                s[mt][nt][1] = __expf(s[mt][nt][1] - mn0);
                s[mt][nt][2] = __expf(s[mt][nt][2] - mn1);
                s[mt][nt][3] = __expf(s[mt][nt][3] - mn1);
                rs0 += s[mt][nt][0] + s[mt][nt][1];
                rs1 += s[mt][nt][2] + s[mt][nt][3];
            }
            rs0 += __shfl_xor_sync(0xffffffffu, rs0, 1);
            rs0 += __shfl_xor_sync(0xffffffffu, rs0, 2);
            rs1 += __shfl_xor_sync(0xffffffffu, rs1, 1);
            rs1 += __shfl_xor_sync(0xffffffffu, rs1, 2);
            lsum[mt][0] = lsum[mt][0] * sc0 + rs0;
            lsum[mt][1] = lsum[mt][1] * sc1 + rs1;
            mx[mt][0] = mn0; mx[mt][1] = mn1;
#pragma unroll
            for (int nt = 0; nt < 8; nt++) {
                o[mt][nt][0] *= sc0; o[mt][nt][1] *= sc0;
                o[mt][nt][2] *= sc1; o[mt][nt][3] *= sc1;
            }
        }

        // ---- O += P V  (V-frag reused across 2 m-tiles; P via shuffles) ----
#pragma unroll
        for (int ct = 0; ct < 8; ct++) {
            float pa[2][4];
#pragma unroll
            for (int mt = 0; mt < 2; mt++) {
                float v00 = __shfl_sync(0xffffffffu, s[mt][ct][0], sidx);
                float v01 = __shfl_sync(0xffffffffu, s[mt][ct][1], sidx);
                float v10 = __shfl_sync(0xffffffffu, s[mt][ct][2], sidx);
                float v11 = __shfl_sync(0xffffffffu, s[mt][ct][3], sidx);
                float w00 = __shfl_sync(0xffffffffu, s[mt][ct][0], sidx + 2);
                float w01 = __shfl_sync(0xffffffffu, s[mt][ct][1], sidx + 2);
                float w10 = __shfl_sync(0xffffffffu, s[mt][ct][2], sidx + 2);
                float w11 = __shfl_sync(0xffffffffu, s[mt][ct][3], sidx + 2);
                pa[mt][0] = (t & 1) ? v01 : v00;
                pa[mt][1] = (t & 1) ? v11 : v10;
                pa[mt][2] = (t & 1) ? w01 : w00;
                pa[mt][3] = (t & 1) ? w11 : w10;
            }
            const float* vb = &Vs[g * KW + 8 * ct + t];
#pragma unroll
            for (int nt = 0; nt < 8; nt++) {
                float b0 = vb[8 * nt * KW], b1 = vb[8 * nt * KW + 4];
                MMA_F(o[0][nt], pa[0][0], pa[0][1], pa[0][2], pa[0][3], b0, b1);
                MMA_F(o[1][nt], pa[1][0], pa[1][1], pa[1][2], pa[1][3], b0, b1);
            }
        }
    }
#undef KV_ISSUE

    size_t hb = (size_t)b * Cc + (size_t)h * CHd;
#pragma unroll
    for (int mt = 0; mt < 2; mt++) {
        float il0 = 1.0f / lsum[mt][0], il1 = 1.0f / lsum[mt][1];
#pragma unroll
        for (int nt = 0; nt < 8; nt++) {
            int d = 8 * nt + cb;
            size_t base = (hb + d) * Tt + q0 + 32 * w + 16 * mt;
            g_a[base + g]          = o[mt][nt][0] * il0;
            g_a[base + Tt + g]     = o[mt][nt][1] * il0;
            g_a[base + g + 8]      = o[mt][nt][2] * il1;
            g_a[base + Tt + g + 8] = o[mt][nt][3] * il1;
        }
    }
}

// ---------------- launch ----------------
extern "C" void kernel_launch(void* const* d_in, const int* in_sizes, int n_in,
                              void* d_out, int out_size) {
    const float* x       = (const float*)d_in[0];
    const float* gn_w    = (const float*)d_in[1];
    const float* gn_b    = (const float*)d_in[2];
    const float* qkv_w   = (const float*)d_in[3];
    const float* qkv_b   = (const float*)d_in[4];
    const float* proj_w  = (const float*)d_in[5];
    const float* proj_b  = (const float*)d_in[6];
    const float* rel_emb = (const float*)d_in[7];
    float* out = (float*)d_out;
    (void)in_sizes; (void)n_in; (void)out_size;

    cudaFuncSetAttribute(mma_gemm<false>, cudaFuncAttributeMaxDynamicSharedMemorySize, GEMM_SMEM);
    cudaFuncSetAttribute(mma_gemm<true>,  cudaFuncAttributeMaxDynamicSharedMemorySize, GEMM_SMEM);
    cudaFuncSetAttribute(attn_kernel, cudaFuncAttributeMaxDynamicSharedMemorySize, ATTN_SMEM);

    fill_tab_kernel<<<(Hh * (2 * Tt - 1) + 255) / 256, 256>>>(rel_emb);
    gn_kernel<<<Bq * Gg, 256>>>(x, gn_w, gn_b);
    mma_gemm<false><<<dim3(Tt / 128, (3 * Cc) / 128, Bq), 256, GEMM_SMEM>>>(qkv_w, qkv_b, nullptr, nullptr);
    attn_kernel<<<dim3(Tt / 128, Hh, Bq), 128, ATTN_SMEM>>>();
    mma_gemm<true><<<dim3(Tt / 128, Cc / 128, Bq), 256, GEMM_SMEM>>>(proj_w, proj_b, x, out);
}